// round 7
// baseline (speedup 1.0000x reference)
#include <cuda_runtime.h>

#define NQ      10
#define DIM     1024
#define NLAYERS 6
#define BATCH   16384

// Precomputed tables (sample-independent):
//  g_ry[l][q] = (cos θ/2, sin θ/2)
//  g_T0[idx]  = init phase pairs: (-i)^popc(n) * Dphi_0[n]
//  g_E[l-1][idx] = fused diagonal between RY layer l-1 and l
// idx = k*32 + lane; pair covers amplitudes n0 = lane*32+k*2, n1 = n0+1
__device__ float2 g_ry[NLAYERS][NQ];
__device__ __align__(16) float4 g_T0[512];
__device__ __align__(16) float4 g_E[5][512];

// ---------------------------------------------------------------------------
// Compile-time GF(2) algebra for the final CNOT layer (r=6), virtualized into
// the epilogue.
// ---------------------------------------------------------------------------
__host__ __device__ constexpr int s6inv_map(int m) {
    for (int w = 0; w < 10; ++w) {
        int cb = 9 - w, tb = 9 - ((w + 6) % 10);
        m ^= ((m >> cb) & 1) << tb;
    }
    return m;
}
__host__ __device__ constexpr int s6inv_row_bit(int b) {
    int r = 0;
    for (int j = 0; j < 10; ++j)
        r |= ((s6inv_map(1 << j) >> b) & 1) << j;
    return r;
}

// ---------------------------------------------------------------------------
// Packed f32x2 helpers (SASS FFMA2/FMUL2 — ptxas never emits these from C++)
// ---------------------------------------------------------------------------
__device__ __forceinline__ float2 ffma2_(float2 a, float2 b, float2 c) {
    float2 d;
    asm("{\n\t.reg .b64 A,B,C,D;\n\t"
        "mov.b64 A,{%2,%3};\n\t mov.b64 B,{%4,%5};\n\t mov.b64 C,{%6,%7};\n\t"
        "fma.rn.f32x2 D,A,B,C;\n\t"
        "mov.b64 {%0,%1},D;\n\t}"
        : "=f"(d.x), "=f"(d.y)
        : "f"(a.x), "f"(a.y), "f"(b.x), "f"(b.y), "f"(c.x), "f"(c.y));
    return d;
}
__device__ __forceinline__ float2 fmul2_(float2 a, float2 b) {
    float2 d;
    asm("{\n\t.reg .b64 A,B,D;\n\t"
        "mov.b64 A,{%2,%3};\n\t mov.b64 B,{%4,%5};\n\t"
        "mul.rn.f32x2 D,A,B;\n\t"
        "mov.b64 {%0,%1},D;\n\t}"
        : "=f"(d.x), "=f"(d.y)
        : "f"(a.x), "f"(a.y), "f"(b.x), "f"(b.y));
    return d;
}
__device__ __forceinline__ float2 fsub2_(float2 a, float2 b) {
    float2 d;
    asm("{\n\t.reg .b64 A,B,D;\n\t"
        "mov.b64 A,{%2,%3};\n\t mov.b64 B,{%4,%5};\n\t"
        "sub.rn.f32x2 D,A,B;\n\t"
        "mov.b64 {%0,%1},D;\n\t}"
        : "=f"(d.x), "=f"(d.y)
        : "f"(a.x), "f"(a.y), "f"(b.x), "f"(b.y));
    return d;
}
__device__ __forceinline__ float2 bc2(float v) { return make_float2(v, v); }

// ---------------------------------------------------------------------------
// Pre-kernel: RY coefficients + diagonal phase tables.
// ---------------------------------------------------------------------------
__device__ __forceinline__ float sum_signed(int n, const float* ql, int l, int off) {
    float a = 0.f;
    #pragma unroll
    for (int q = 0; q < NQ; ++q) {
        float v = ql[(l * NQ + q) * 3 + off];
        a += ((n >> (9 - q)) & 1) ? v : -v;
    }
    return 0.5f * a;
}

__global__ void table_kernel(const float* __restrict__ ql) {
    int idx = blockIdx.x * blockDim.x + threadIdx.x;
    if (idx < NLAYERS * NQ) {
        int l = idx / NQ, q = idx % NQ;
        float s, c; sincosf(0.5f * ql[(l * NQ + q) * 3 + 1], &s, &c);
        g_ry[l][q] = make_float2(c, s);
    }
    if (idx >= 512) return;
    int k = idx >> 5, lane = idx & 31;
    int n0 = lane * 32 + k * 2;

    {   // T0: (-i)^popc(n) * Dphi_0[n]
        float cs[2], sn[2];
        #pragma unroll
        for (int comp = 0; comp < 2; ++comp) {
            int n = n0 + comp;
            float ang = -1.57079632679f * __popc(n) + sum_signed(n, ql, 0, 0);
            sincosf(ang, &sn[comp], &cs[comp]);
        }
        g_T0[idx] = make_float4(cs[0], sn[0], cs[1], sn[1]);
    }
    // E_l for l = 1..5: E[m] = Domega_{l-1}[m] * Dphi_l[sigma_{l-1}^{-1}(m)]
    #pragma unroll 1
    for (int l = 1; l <= 5; ++l) {
        float cs[2], sn[2];
        #pragma unroll
        for (int comp = 0; comp < 2; ++comp) {
            int n = n0 + comp;
            float angw = sum_signed(n, ql, l - 1, 2);
            int p = n;             // sigma^{-1}: apply tau_0 .. tau_9 in order
            #pragma unroll
            for (int w = 0; w < NQ; ++w) {
                int cbit = 9 - w;
                int tbit = 9 - ((w + l) % NQ);
                p ^= ((p >> cbit) & 1) << tbit;
            }
            float angp = sum_signed(p, ql, l, 0);
            sincosf(angw + angp, &sn[comp], &cs[comp]);
        }
        g_E[l - 1][idx] = make_float4(cs[0], sn[0], cs[1], sn[1]);
    }
}

// ---------------------------------------------------------------------------
// State layout: amplitude n: bits 9..5 lane, 4..1 pack k, 0 comp.
// Qubit q acts on bit 9-q.
// ---------------------------------------------------------------------------

// Plain RY gate on lane bit L.
template<int L>
__device__ __forceinline__ void ry_lane_gate(float2 sr[16], float2 si[16], int lane,
                                             float2 g) {
    constexpr unsigned msk = 1u << L;
    const bool hi = (lane >> L) & 1;
    const float2 c2 = bc2(g.x);
    const float2 s2 = bc2(hi ? g.y : -g.y);
    #pragma unroll
    for (int k = 0; k < 16; ++k) {
        float2 qr, qi;
        qr.x = __shfl_xor_sync(0xffffffffu, sr[k].x, msk);
        qr.y = __shfl_xor_sync(0xffffffffu, sr[k].y, msk);
        qi.x = __shfl_xor_sync(0xffffffffu, si[k].x, msk);
        qi.y = __shfl_xor_sync(0xffffffffu, si[k].y, msk);
        sr[k] = ffma2_(s2, qr, fmul2_(c2, sr[k]));
        si[k] = ffma2_(s2, qi, fmul2_(c2, si[k]));
    }
}

// Plain RY gate on local bit B (1..4 = pack bit B-1; 0 = comp bit).
template<int B>
__device__ __forceinline__ void ry_local_gate(float2 sr[16], float2 si[16], float2 g) {
    if constexpr (B >= 1) {
        constexpr int pb = B - 1;
        const float2 cl2 = bc2(g.x), sl2 = bc2(g.y), nsl2 = bc2(-g.y);
        #pragma unroll
        for (int t = 0; t < 8; ++t) {
            const int k  = ((t >> pb) << (pb + 1)) | (t & ((1 << pb) - 1));
            const int k2 = k | (1 << pb);
            float2 Ar = sr[k], Ai = si[k], Br = sr[k2], Bi = si[k2];
            sr[k]  = ffma2_(nsl2, Br, fmul2_(cl2, Ar));
            si[k]  = ffma2_(nsl2, Bi, fmul2_(cl2, Ai));
            sr[k2] = ffma2_(cl2, Br, fmul2_(sl2, Ar));
            si[k2] = ffma2_(cl2, Bi, fmul2_(sl2, Ai));
        }
    } else {
        const float2 c2 = bc2(g.x);
        const float2 sp2 = make_float2(-g.y, g.y);
        #pragma unroll
        for (int k = 0; k < 16; ++k) {
            float2 vr = sr[k], vi = si[k];
            float2 wr = make_float2(vr.y, vr.x);
            float2 wi = make_float2(vi.y, vi.x);
            sr[k] = ffma2_(sp2, wr, fmul2_(c2, vr));
            si[k] = ffma2_(sp2, wi, fmul2_(c2, vi));
        }
    }
}

// Fused stage: CNOT(local control bit Bc -> lane target bit L) + RY(target).
template<int Bc, int L>
__device__ __forceinline__ void fused_cnot_ry(float2 sr[16], float2 si[16], int lane,
                                              float2 g) {
    constexpr unsigned msk = 1u << L;
    const bool hi = (lane >> L) & 1;
    const float sg = hi ? g.y : -g.y;
    if constexpr (Bc == 0) {
        const float2 A = make_float2(g.x, sg);
        const float2 B = make_float2(sg, g.x);
        #pragma unroll
        for (int k = 0; k < 16; ++k) {
            float2 qr, qi;
            qr.x = __shfl_xor_sync(0xffffffffu, sr[k].x, msk);
            qr.y = __shfl_xor_sync(0xffffffffu, sr[k].y, msk);
            qi.x = __shfl_xor_sync(0xffffffffu, si[k].x, msk);
            qi.y = __shfl_xor_sync(0xffffffffu, si[k].y, msk);
            sr[k] = ffma2_(B, qr, fmul2_(A, sr[k]));
            si[k] = ffma2_(B, qi, fmul2_(A, si[k]));
        }
    } else {
        const float2 c2 = bc2(g.x), s2 = bc2(sg);
        #pragma unroll
        for (int k = 0; k < 16; ++k) {
            float2 qr, qi;
            qr.x = __shfl_xor_sync(0xffffffffu, sr[k].x, msk);
            qr.y = __shfl_xor_sync(0xffffffffu, sr[k].y, msk);
            qi.x = __shfl_xor_sync(0xffffffffu, si[k].x, msk);
            qi.y = __shfl_xor_sync(0xffffffffu, si[k].y, msk);
            const bool ctl = (k >> (Bc - 1)) & 1;       // compile-time after unroll
            const float2 A = ctl ? s2 : c2;
            const float2 B = ctl ? c2 : s2;
            sr[k] = ffma2_(B, qr, fmul2_(A, sr[k]));
            si[k] = ffma2_(B, qi, fmul2_(A, si[k]));
        }
    }
}

// ---------------------------------------------------------------------------
// Standalone CNOT: control bit BC, target bit BT.
// ---------------------------------------------------------------------------
template<int BC, int BT>
__device__ __forceinline__ void cnot_gate(float2 sr[16], float2 si[16], int lane) {
    if constexpr (BC >= 5 && BT >= 5) {
        // lane ctrl, lane target: variable-source shuffle — the conditional
        // exchange folds into the shuffle source operand (no SELs at all).
        constexpr unsigned msk = 1u << (BT - 5);
        const int src = ((lane >> (BC - 5)) & 1) ? (lane ^ (int)msk) : lane;
        #pragma unroll
        for (int k = 0; k < 16; ++k) {
            sr[k].x = __shfl_sync(0xffffffffu, sr[k].x, src);
            sr[k].y = __shfl_sync(0xffffffffu, sr[k].y, src);
            si[k].x = __shfl_sync(0xffffffffu, si[k].x, src);
            si[k].y = __shfl_sync(0xffffffffu, si[k].y, src);
        }
    } else if constexpr (BC >= 5 && BT >= 1) {
        constexpr int pb = BT - 1;
        const bool ctl = (lane >> (BC - 5)) & 1;
        #pragma unroll
        for (int k = 0; k < 16; ++k) {
            if (!((k >> pb) & 1)) {
                const int k2 = k | (1 << pb);
                float2 r0 = sr[k], r1 = sr[k2];
                float2 i0 = si[k], i1 = si[k2];
                sr[k].x  = ctl ? r1.x : r0.x;  sr[k].y  = ctl ? r1.y : r0.y;
                sr[k2].x = ctl ? r0.x : r1.x;  sr[k2].y = ctl ? r0.y : r1.y;
                si[k].x  = ctl ? i1.x : i0.x;  si[k].y  = ctl ? i1.y : i0.y;
                si[k2].x = ctl ? i0.x : i1.x;  si[k2].y = ctl ? i0.y : i1.y;
            }
        }
    } else if constexpr (BC >= 5 && BT == 0) {
        const bool ctl = (lane >> (BC - 5)) & 1;
        #pragma unroll
        for (int k = 0; k < 16; ++k) {
            float2 vr = sr[k], vi = si[k];
            sr[k].x = ctl ? vr.y : vr.x;  sr[k].y = ctl ? vr.x : vr.y;
            si[k].x = ctl ? vi.y : vi.x;  si[k].y = ctl ? vi.x : vi.y;
        }
    } else if constexpr (BC >= 1 && BT >= 5) {
        constexpr unsigned msk = 1u << (BT - 5);
        constexpr int pb = BC - 1;
        #pragma unroll
        for (int k = 0; k < 16; ++k) {
            if ((k >> pb) & 1) {
                sr[k].x = __shfl_xor_sync(0xffffffffu, sr[k].x, msk);
                sr[k].y = __shfl_xor_sync(0xffffffffu, sr[k].y, msk);
                si[k].x = __shfl_xor_sync(0xffffffffu, si[k].x, msk);
                si[k].y = __shfl_xor_sync(0xffffffffu, si[k].y, msk);
            }
        }
    } else if constexpr (BC >= 1 && BT >= 1) {
        constexpr int pbc = BC - 1, pbt = BT - 1;
        #pragma unroll
        for (int k = 0; k < 16; ++k) {
            if (((k >> pbc) & 1) && !((k >> pbt) & 1)) {
                const int k2 = k | (1 << pbt);
                float2 t;
                t = sr[k]; sr[k] = sr[k2]; sr[k2] = t;
                t = si[k]; si[k] = si[k2]; si[k2] = t;
            }
        }
    } else if constexpr (BC >= 1 && BT == 0) {
        constexpr int pb = BC - 1;
        #pragma unroll
        for (int k = 0; k < 16; ++k) {
            if ((k >> pb) & 1) {
                float t;
                t = sr[k].x; sr[k].x = sr[k].y; sr[k].y = t;
                t = si[k].x; si[k].x = si[k].y; si[k].y = t;
            }
        }
    } else if constexpr (BC == 0 && BT >= 5) {
        constexpr unsigned msk = 1u << (BT - 5);
        #pragma unroll
        for (int k = 0; k < 16; ++k) {
            sr[k].y = __shfl_xor_sync(0xffffffffu, sr[k].y, msk);
            si[k].y = __shfl_xor_sync(0xffffffffu, si[k].y, msk);
        }
    } else {
        constexpr int pb = BT - 1;
        #pragma unroll
        for (int k = 0; k < 16; ++k) {
            if (!((k >> pb) & 1)) {
                const int k2 = k | (1 << pb);
                float t;
                t = sr[k].y; sr[k].y = sr[k2].y; sr[k2].y = t;
                t = si[k].y; si[k].y = si[k2].y; si[k2].y = t;
            }
        }
    }
}

// fused diagonal: per pack complex multiply by table phase
__device__ __forceinline__ void apply_diag(float2 sr[16], float2 si[16], int lane,
                                           const float4* __restrict__ tbl) {
    #pragma unroll
    for (int k = 0; k < 16; ++k) {
        float4 t = __ldg(tbl + k * 32 + lane);
        float2 c = make_float2(t.x, t.z);
        float2 s = make_float2(t.y, t.w);
        float2 r = sr[k], i = si[k];
        sr[k] = fsub2_(fmul2_(c, r), fmul2_(s, i));
        si[k] = ffma2_(c, i, fmul2_(s, r));
    }
}

// ---------------------------------------------------------------------------
// Layer scheduling (layer l, CNOT shift r = l):
//  1. diag E_l
//  2. standalone taus w = 0..9-r  (no wrap; index order)
//  3. fused stages   w = 10-r..9: CNOT(ctl bit 9-w local, tgt bit 19-w-r lane)
//     + RY gate on qubit w+r-10
//  4. remaining RY gates q = r..9
// ---------------------------------------------------------------------------
template<int R, int W>
__device__ __forceinline__ void standalone_taus(float2 sr[16], float2 si[16], int lane) {
    if constexpr (W <= 9 - R) {
        cnot_gate<9 - W, 9 - W - R>(sr, si, lane);
        standalone_taus<R, W + 1>(sr, si, lane);
    }
}
template<int R, int W>
__device__ __forceinline__ void fused_stages(float2 sr[16], float2 si[16], int lane,
                                             const float2* __restrict__ ry) {
    if constexpr (W <= 9) {
        constexpr int Bc = 9 - W;          // local control bit (0..R-1)
        constexpr int Bt = 19 - W - R;     // lane target bit (5..9)
        fused_cnot_ry<Bc, Bt - 5>(sr, si, lane, __ldg(ry + (W + R - 10)));
        fused_stages<R, W + 1>(sr, si, lane, ry);
    }
}
template<int R, int Q>
__device__ __forceinline__ void remaining_gates(float2 sr[16], float2 si[16], int lane,
                                                const float2* __restrict__ ry) {
    if constexpr (Q <= 9) {
        if constexpr (Q <= 4)
            ry_lane_gate<4 - Q>(sr, si, lane, __ldg(ry + Q));
        else
            ry_local_gate<9 - Q>(sr, si, __ldg(ry + Q));
        remaining_gates<R, Q + 1>(sr, si, lane, ry);
    }
}
template<int L>
__device__ __forceinline__ void fused_layer(float2 sr[16], float2 si[16], int lane) {
    apply_diag(sr, si, lane, g_E[L - 1]);
    standalone_taus<L, 0>(sr, si, lane);
    fused_stages<L, 10 - L>(sr, si, lane, g_ry[L]);
    remaining_gates<L, L>(sr, si, lane, g_ry[L]);
}

// ---------------------------------------------------------------------------
// Main kernel. Block 128, min 5 CTAs/SM -> 102-reg target, 20 warps/SM.
// ---------------------------------------------------------------------------
__global__ void __launch_bounds__(128, 5) qcnn_kernel(
    const float* __restrict__ x,
    const float* __restrict__ fc_w,
    const float* __restrict__ fc_b,
    float* __restrict__ out)
{
    const int warp = (blockIdx.x * blockDim.x + threadIdx.x) >> 5;
    const int lane = threadIdx.x & 31;
    if (warp >= BATCH) return;

    // --- initial product state magnitudes -----------------------------------
    const float* xb = x + warp * NQ;
    float cq[NQ], sq[NQ];
    #pragma unroll
    for (int q = 0; q < NQ; ++q) {
        float h = 0.5f * __ldg(xb + q);
        sincosf(h, &sq[q], &cq[q]);
    }
    float A = 1.f;
    #pragma unroll
    for (int q = 0; q < 5; ++q)
        A *= ((lane >> (4 - q)) & 1) ? sq[q] : cq[q];

    float m[16];
    m[0] = A;
    #pragma unroll
    for (int t = 0; t < 4; ++t) {
        const int q = 8 - t;
        const int sz = 1 << t;
        #pragma unroll
        for (int k = sz - 1; k >= 0; --k) {
            float v = m[k];
            m[k + sz] = v * sq[q];
            m[k]      = v * cq[q];
        }
    }
    float2 sr[16], si[16];
    #pragma unroll
    for (int k = 0; k < 16; ++k) {
        float4 t = __ldg(&g_T0[k * 32 + lane]);
        float2 mag2 = make_float2(m[k] * cq[9], m[k] * sq[9]);
        sr[k] = fmul2_(mag2, make_float2(t.x, t.z));
        si[k] = fmul2_(mag2, make_float2(t.y, t.w));
    }

    // --- circuit -------------------------------------------------------------
    remaining_gates<0, 0>(sr, si, lane, g_ry[0]);   // Y_0 (no preceding P)
    fused_layer<1>(sr, si, lane);
    fused_layer<2>(sr, si, lane);
    fused_layer<3>(sr, si, lane);
    fused_layer<4>(sr, si, lane);
    fused_layer<5>(sr, si, lane);
    // P_5 (r=6) fully virtualized into the epilogue weights below.

    // --- epilogue: out = sum_m w_{S6^{-1} m} |psi_m|^2 -----------------------
    float F[NQ];
    #pragma unroll
    for (int q = 0; q < NQ; ++q) {
        const int lm = (s6inv_row_bit(9 - q) >> 5) & 31;   // constant-folded
        float fq = __ldg(fc_w + q);
        F[q] = (__popc(lane & lm) & 1) ? -fq : fq;
    }
    float2 acc2 = make_float2(0.f, 0.f);
    #pragma unroll
    for (int k = 0; k < 16; ++k) {
        float w0 = 0.f, w1 = 0.f;
        #pragma unroll
        for (int q = 0; q < NQ; ++q) {
            const int pm = s6inv_row_bit(9 - q) & 31;      // constant-folded
            w0 = (__popc((k << 1) & pm) & 1)       ? (w0 - F[q]) : (w0 + F[q]);
            w1 = (__popc(((k << 1) | 1) & pm) & 1) ? (w1 - F[q]) : (w1 + F[q]);
        }
        float2 p2 = ffma2_(si[k], si[k], fmul2_(sr[k], sr[k]));
        acc2 = ffma2_(make_float2(w0, w1), p2, acc2);
    }
    float acc = acc2.x + acc2.y;
    #pragma unroll
    for (int off = 16; off; off >>= 1)
        acc += __shfl_xor_sync(0xffffffffu, acc, off);

    if (lane == 0) out[warp] = acc + __ldg(fc_b);
}

// ---------------------------------------------------------------------------
extern "C" void kernel_launch(void* const* d_in, const int* in_sizes, int n_in,
                              void* d_out, int out_size) {
    const float* x    = (const float*)d_in[0];   // (16384, 10)
    const float* ql   = (const float*)d_in[1];   // (6, 10, 3)
    const float* fcw  = (const float*)d_in[2];   // (1, 10)
    const float* fcb  = (const float*)d_in[3];   // (1,)
    float* out = (float*)d_out;                  // (16384, 1)

    table_kernel<<<2, 256>>>(ql);
    qcnn_kernel<<<BATCH / 4, 128>>>(x, fcw, fcb, out);
}

// round 8
// speedup vs baseline: 1.1399x; 1.1399x over previous
#include <cuda_runtime.h>

#define NQ      10
#define DIM     1024
#define NLAYERS 6
#define BATCH   16384

// Precomputed tables (sample-independent):
//  g_ry[l][q] = (cos θ/2, sin θ/2)
//  g_T0[idx]  = init phase pairs: (-i)^popc(n) * Dphi_0[n]
//  g_E[l-1][idx] = fused diagonal between RY layer l-1 and l
//  g_W[idx]   = epilogue weights w_{S6^{-1} n} for the pair (n0, n0+1)
// idx = k*32 + lane; pair covers amplitudes n0 = lane*32+k*2, n1 = n0+1
__device__ float2 g_ry[NLAYERS][NQ];
__device__ __align__(16) float4 g_T0[512];
__device__ __align__(16) float4 g_E[5][512];
__device__ __align__(8)  float2 g_W[512];

// ---------------------------------------------------------------------------
// GF(2) algebra for the final CNOT layer (r=6), virtualized into the epilogue.
// ---------------------------------------------------------------------------
__host__ __device__ constexpr int s6inv_map(int m) {
    for (int w = 0; w < 10; ++w) {
        int cb = 9 - w, tb = 9 - ((w + 6) % 10);
        m ^= ((m >> cb) & 1) << tb;
    }
    return m;
}

// ---------------------------------------------------------------------------
// Packed f32x2 helpers (SASS FFMA2/FMUL2 — ptxas never emits these from C++)
// ---------------------------------------------------------------------------
__device__ __forceinline__ float2 ffma2_(float2 a, float2 b, float2 c) {
    float2 d;
    asm("{\n\t.reg .b64 A,B,C,D;\n\t"
        "mov.b64 A,{%2,%3};\n\t mov.b64 B,{%4,%5};\n\t mov.b64 C,{%6,%7};\n\t"
        "fma.rn.f32x2 D,A,B,C;\n\t"
        "mov.b64 {%0,%1},D;\n\t}"
        : "=f"(d.x), "=f"(d.y)
        : "f"(a.x), "f"(a.y), "f"(b.x), "f"(b.y), "f"(c.x), "f"(c.y));
    return d;
}
__device__ __forceinline__ float2 fmul2_(float2 a, float2 b) {
    float2 d;
    asm("{\n\t.reg .b64 A,B,D;\n\t"
        "mov.b64 A,{%2,%3};\n\t mov.b64 B,{%4,%5};\n\t"
        "mul.rn.f32x2 D,A,B;\n\t"
        "mov.b64 {%0,%1},D;\n\t}"
        : "=f"(d.x), "=f"(d.y)
        : "f"(a.x), "f"(a.y), "f"(b.x), "f"(b.y));
    return d;
}
__device__ __forceinline__ float2 fsub2_(float2 a, float2 b) {
    float2 d;
    asm("{\n\t.reg .b64 A,B,D;\n\t"
        "mov.b64 A,{%2,%3};\n\t mov.b64 B,{%4,%5};\n\t"
        "sub.rn.f32x2 D,A,B;\n\t"
        "mov.b64 {%0,%1},D;\n\t}"
        : "=f"(d.x), "=f"(d.y)
        : "f"(a.x), "f"(a.y), "f"(b.x), "f"(b.y));
    return d;
}
__device__ __forceinline__ float2 bc2(float v) { return make_float2(v, v); }

// ---------------------------------------------------------------------------
// Pre-kernel: RY coefficients + diagonal phase tables + epilogue weights.
// ---------------------------------------------------------------------------
__device__ __forceinline__ float sum_signed(int n, const float* ql, int l, int off) {
    float a = 0.f;
    #pragma unroll
    for (int q = 0; q < NQ; ++q) {
        float v = ql[(l * NQ + q) * 3 + off];
        a += ((n >> (9 - q)) & 1) ? v : -v;
    }
    return 0.5f * a;
}

__global__ void table_kernel(const float* __restrict__ ql,
                             const float* __restrict__ fcw) {
    int idx = blockIdx.x * blockDim.x + threadIdx.x;
    if (idx < NLAYERS * NQ) {
        int l = idx / NQ, q = idx % NQ;
        float s, c; sincosf(0.5f * ql[(l * NQ + q) * 3 + 1], &s, &c);
        g_ry[l][q] = make_float2(c, s);
    }
    if (idx >= 512) return;
    int k = idx >> 5, lane = idx & 31;
    int n0 = lane * 32 + k * 2;

    {   // T0: (-i)^popc(n) * Dphi_0[n]
        float cs[2], sn[2];
        #pragma unroll
        for (int comp = 0; comp < 2; ++comp) {
            int n = n0 + comp;
            float ang = -1.57079632679f * __popc(n) + sum_signed(n, ql, 0, 0);
            sincosf(ang, &sn[comp], &cs[comp]);
        }
        g_T0[idx] = make_float4(cs[0], sn[0], cs[1], sn[1]);
    }
    // E_l for l = 1..5: E[m] = Domega_{l-1}[m] * Dphi_l[sigma_{l-1}^{-1}(m)]
    #pragma unroll 1
    for (int l = 1; l <= 5; ++l) {
        float cs[2], sn[2];
        #pragma unroll
        for (int comp = 0; comp < 2; ++comp) {
            int n = n0 + comp;
            float angw = sum_signed(n, ql, l - 1, 2);
            int p = n;             // sigma^{-1}: apply tau_0 .. tau_9 in order
            #pragma unroll
            for (int w = 0; w < NQ; ++w) {
                int cbit = 9 - w;
                int tbit = 9 - ((w + l) % NQ);
                p ^= ((p >> cbit) & 1) << tbit;
            }
            float angp = sum_signed(p, ql, l, 0);
            sincosf(angw + angp, &sn[comp], &cs[comp]);
        }
        g_E[l - 1][idx] = make_float4(cs[0], sn[0], cs[1], sn[1]);
    }
    {   // Epilogue weights: w[n] = sum_q fcw[q] * (1 - 2*bit_{9-q}(S6^{-1} n))
        float wv[2];
        #pragma unroll
        for (int comp = 0; comp < 2; ++comp) {
            int p = s6inv_map(n0 + comp);
            float a = 0.f;
            #pragma unroll
            for (int q = 0; q < NQ; ++q) {
                float v = fcw[q];
                a += ((p >> (9 - q)) & 1) ? -v : v;
            }
            wv[comp] = a;
        }
        g_W[idx] = make_float2(wv[0], wv[1]);
    }
}

// ---------------------------------------------------------------------------
// State layout: amplitude n: bits 9..5 lane, 4..1 pack k, 0 comp.
// Qubit q acts on bit 9-q.
// ---------------------------------------------------------------------------

// Plain RY gate on lane bit L.
template<int L>
__device__ __forceinline__ void ry_lane_gate(float2 sr[16], float2 si[16], int lane,
                                             float2 g) {
    constexpr unsigned msk = 1u << L;
    const bool hi = (lane >> L) & 1;
    const float2 c2 = bc2(g.x);
    const float2 s2 = bc2(hi ? g.y : -g.y);
    #pragma unroll
    for (int k = 0; k < 16; ++k) {
        float2 qr, qi;
        qr.x = __shfl_xor_sync(0xffffffffu, sr[k].x, msk);
        qr.y = __shfl_xor_sync(0xffffffffu, sr[k].y, msk);
        qi.x = __shfl_xor_sync(0xffffffffu, si[k].x, msk);
        qi.y = __shfl_xor_sync(0xffffffffu, si[k].y, msk);
        sr[k] = ffma2_(s2, qr, fmul2_(c2, sr[k]));
        si[k] = ffma2_(s2, qi, fmul2_(c2, si[k]));
    }
}

// Plain RY gate on local bit B (1..4 = pack bit B-1; 0 = comp bit).
template<int B>
__device__ __forceinline__ void ry_local_gate(float2 sr[16], float2 si[16], float2 g) {
    if constexpr (B >= 1) {
        constexpr int pb = B - 1;
        const float2 cl2 = bc2(g.x), sl2 = bc2(g.y), nsl2 = bc2(-g.y);
        #pragma unroll
        for (int t = 0; t < 8; ++t) {
            const int k  = ((t >> pb) << (pb + 1)) | (t & ((1 << pb) - 1));
            const int k2 = k | (1 << pb);
            float2 Ar = sr[k], Ai = si[k], Br = sr[k2], Bi = si[k2];
            sr[k]  = ffma2_(nsl2, Br, fmul2_(cl2, Ar));
            si[k]  = ffma2_(nsl2, Bi, fmul2_(cl2, Ai));
            sr[k2] = ffma2_(cl2, Br, fmul2_(sl2, Ar));
            si[k2] = ffma2_(cl2, Bi, fmul2_(sl2, Ai));
        }
    } else {
        const float2 c2 = bc2(g.x);
        const float2 sp2 = make_float2(-g.y, g.y);
        #pragma unroll
        for (int k = 0; k < 16; ++k) {
            float2 vr = sr[k], vi = si[k];
            float2 wr = make_float2(vr.y, vr.x);
            float2 wi = make_float2(vi.y, vi.x);
            sr[k] = ffma2_(sp2, wr, fmul2_(c2, vr));
            si[k] = ffma2_(sp2, wi, fmul2_(c2, vi));
        }
    }
}

// Fused stage: CNOT(local control bit Bc -> lane target bit L) + RY(target).
template<int Bc, int L>
__device__ __forceinline__ void fused_cnot_ry(float2 sr[16], float2 si[16], int lane,
                                              float2 g) {
    constexpr unsigned msk = 1u << L;
    const bool hi = (lane >> L) & 1;
    const float sg = hi ? g.y : -g.y;
    if constexpr (Bc == 0) {
        const float2 A = make_float2(g.x, sg);
        const float2 B = make_float2(sg, g.x);
        #pragma unroll
        for (int k = 0; k < 16; ++k) {
            float2 qr, qi;
            qr.x = __shfl_xor_sync(0xffffffffu, sr[k].x, msk);
            qr.y = __shfl_xor_sync(0xffffffffu, sr[k].y, msk);
            qi.x = __shfl_xor_sync(0xffffffffu, si[k].x, msk);
            qi.y = __shfl_xor_sync(0xffffffffu, si[k].y, msk);
            sr[k] = ffma2_(B, qr, fmul2_(A, sr[k]));
            si[k] = ffma2_(B, qi, fmul2_(A, si[k]));
        }
    } else {
        const float2 c2 = bc2(g.x), s2 = bc2(sg);
        #pragma unroll
        for (int k = 0; k < 16; ++k) {
            float2 qr, qi;
            qr.x = __shfl_xor_sync(0xffffffffu, sr[k].x, msk);
            qr.y = __shfl_xor_sync(0xffffffffu, sr[k].y, msk);
            qi.x = __shfl_xor_sync(0xffffffffu, si[k].x, msk);
            qi.y = __shfl_xor_sync(0xffffffffu, si[k].y, msk);
            const bool ctl = (k >> (Bc - 1)) & 1;       // compile-time after unroll
            const float2 A = ctl ? s2 : c2;
            const float2 B = ctl ? c2 : s2;
            sr[k] = ffma2_(B, qr, fmul2_(A, sr[k]));
            si[k] = ffma2_(B, qi, fmul2_(A, si[k]));
        }
    }
}

// ---------------------------------------------------------------------------
// Standalone CNOT: control bit BC, target bit BT.
// ---------------------------------------------------------------------------
template<int BC, int BT>
__device__ __forceinline__ void cnot_gate(float2 sr[16], float2 si[16], int lane) {
    if constexpr (BC >= 5 && BT >= 5) {
        // lane ctrl, lane target: variable-source shuffle — the conditional
        // exchange folds into the shuffle source operand (no SELs at all).
        constexpr unsigned msk = 1u << (BT - 5);
        const int src = ((lane >> (BC - 5)) & 1) ? (lane ^ (int)msk) : lane;
        #pragma unroll
        for (int k = 0; k < 16; ++k) {
            sr[k].x = __shfl_sync(0xffffffffu, sr[k].x, src);
            sr[k].y = __shfl_sync(0xffffffffu, sr[k].y, src);
            si[k].x = __shfl_sync(0xffffffffu, si[k].x, src);
            si[k].y = __shfl_sync(0xffffffffu, si[k].y, src);
        }
    } else if constexpr (BC >= 5 && BT >= 1) {
        constexpr int pb = BT - 1;
        const bool ctl = (lane >> (BC - 5)) & 1;
        #pragma unroll
        for (int k = 0; k < 16; ++k) {
            if (!((k >> pb) & 1)) {
                const int k2 = k | (1 << pb);
                float2 r0 = sr[k], r1 = sr[k2];
                float2 i0 = si[k], i1 = si[k2];
                sr[k].x  = ctl ? r1.x : r0.x;  sr[k].y  = ctl ? r1.y : r0.y;
                sr[k2].x = ctl ? r0.x : r1.x;  sr[k2].y = ctl ? r0.y : r1.y;
                si[k].x  = ctl ? i1.x : i0.x;  si[k].y  = ctl ? i1.y : i0.y;
                si[k2].x = ctl ? i0.x : i1.x;  si[k2].y = ctl ? i0.y : i1.y;
            }
        }
    } else if constexpr (BC >= 5 && BT == 0) {
        const bool ctl = (lane >> (BC - 5)) & 1;
        #pragma unroll
        for (int k = 0; k < 16; ++k) {
            float2 vr = sr[k], vi = si[k];
            sr[k].x = ctl ? vr.y : vr.x;  sr[k].y = ctl ? vr.x : vr.y;
            si[k].x = ctl ? vi.y : vi.x;  si[k].y = ctl ? vi.x : vi.y;
        }
    } else if constexpr (BC >= 1 && BT >= 5) {
        constexpr unsigned msk = 1u << (BT - 5);
        constexpr int pb = BC - 1;
        #pragma unroll
        for (int k = 0; k < 16; ++k) {
            if ((k >> pb) & 1) {
                sr[k].x = __shfl_xor_sync(0xffffffffu, sr[k].x, msk);
                sr[k].y = __shfl_xor_sync(0xffffffffu, sr[k].y, msk);
                si[k].x = __shfl_xor_sync(0xffffffffu, si[k].x, msk);
                si[k].y = __shfl_xor_sync(0xffffffffu, si[k].y, msk);
            }
        }
    } else if constexpr (BC >= 1 && BT >= 1) {
        constexpr int pbc = BC - 1, pbt = BT - 1;
        #pragma unroll
        for (int k = 0; k < 16; ++k) {
            if (((k >> pbc) & 1) && !((k >> pbt) & 1)) {
                const int k2 = k | (1 << pbt);
                float2 t;
                t = sr[k]; sr[k] = sr[k2]; sr[k2] = t;
                t = si[k]; si[k] = si[k2]; si[k2] = t;
            }
        }
    } else if constexpr (BC >= 1 && BT == 0) {
        constexpr int pb = BC - 1;
        #pragma unroll
        for (int k = 0; k < 16; ++k) {
            if ((k >> pb) & 1) {
                float t;
                t = sr[k].x; sr[k].x = sr[k].y; sr[k].y = t;
                t = si[k].x; si[k].x = si[k].y; si[k].y = t;
            }
        }
    } else if constexpr (BC == 0 && BT >= 5) {
        constexpr unsigned msk = 1u << (BT - 5);
        #pragma unroll
        for (int k = 0; k < 16; ++k) {
            sr[k].y = __shfl_xor_sync(0xffffffffu, sr[k].y, msk);
            si[k].y = __shfl_xor_sync(0xffffffffu, si[k].y, msk);
        }
    } else {
        constexpr int pb = BT - 1;
        #pragma unroll
        for (int k = 0; k < 16; ++k) {
            if (!((k >> pb) & 1)) {
                const int k2 = k | (1 << pb);
                float t;
                t = sr[k].y; sr[k].y = sr[k2].y; sr[k2].y = t;
                t = si[k].y; si[k].y = si[k2].y; si[k2].y = t;
            }
        }
    }
}

// fused diagonal: per pack complex multiply by table phase
__device__ __forceinline__ void apply_diag(float2 sr[16], float2 si[16], int lane,
                                           const float4* __restrict__ tbl) {
    #pragma unroll
    for (int k = 0; k < 16; ++k) {
        float4 t = __ldg(tbl + k * 32 + lane);
        float2 c = make_float2(t.x, t.z);
        float2 s = make_float2(t.y, t.w);
        float2 r = sr[k], i = si[k];
        sr[k] = fsub2_(fmul2_(c, r), fmul2_(s, i));
        si[k] = ffma2_(c, i, fmul2_(s, r));
    }
}

// ---------------------------------------------------------------------------
// Layer scheduling (layer l, CNOT shift r = l):
//  1. diag E_l
//  2. standalone taus w = 0..9-r  (no wrap; index order)
//  3. fused stages   w = 10-r..9: CNOT(ctl bit 9-w local, tgt bit 19-w-r lane)
//     + RY gate on qubit w+r-10
//  4. remaining RY gates q = r..9
// ---------------------------------------------------------------------------
template<int R, int W>
__device__ __forceinline__ void standalone_taus(float2 sr[16], float2 si[16], int lane) {
    if constexpr (W <= 9 - R) {
        cnot_gate<9 - W, 9 - W - R>(sr, si, lane);
        standalone_taus<R, W + 1>(sr, si, lane);
    }
}
template<int R, int W>
__device__ __forceinline__ void fused_stages(float2 sr[16], float2 si[16], int lane,
                                             const float2* __restrict__ ry) {
    if constexpr (W <= 9) {
        constexpr int Bc = 9 - W;          // local control bit (0..R-1)
        constexpr int Bt = 19 - W - R;     // lane target bit (5..9)
        fused_cnot_ry<Bc, Bt - 5>(sr, si, lane, __ldg(ry + (W + R - 10)));
        fused_stages<R, W + 1>(sr, si, lane, ry);
    }
}
template<int R, int Q>
__device__ __forceinline__ void remaining_gates(float2 sr[16], float2 si[16], int lane,
                                                const float2* __restrict__ ry) {
    if constexpr (Q <= 9) {
        if constexpr (Q <= 4)
            ry_lane_gate<4 - Q>(sr, si, lane, __ldg(ry + Q));
        else
            ry_local_gate<9 - Q>(sr, si, __ldg(ry + Q));
        remaining_gates<R, Q + 1>(sr, si, lane, ry);
    }
}
template<int L>
__device__ __forceinline__ void fused_layer(float2 sr[16], float2 si[16], int lane) {
    apply_diag(sr, si, lane, g_E[L - 1]);
    standalone_taus<L, 0>(sr, si, lane);
    fused_stages<L, 10 - L>(sr, si, lane, g_ry[L]);
    remaining_gates<L, L>(sr, si, lane, g_ry[L]);
}

// ---------------------------------------------------------------------------
// Main kernel: one warp per sample; 256 thr, 2 CTAs/SM (128 regs, no spill).
// ---------------------------------------------------------------------------
__global__ void __launch_bounds__(256, 2) qcnn_kernel(
    const float* __restrict__ x,
    const float* __restrict__ fc_b,
    float* __restrict__ out)
{
    const int warp = (blockIdx.x * blockDim.x + threadIdx.x) >> 5;
    const int lane = threadIdx.x & 31;
    if (warp >= BATCH) return;

    // --- initial product state magnitudes -----------------------------------
    const float* xb = x + warp * NQ;
    float cq[NQ], sq[NQ];
    #pragma unroll
    for (int q = 0; q < NQ; ++q) {
        float h = 0.5f * __ldg(xb + q);
        sincosf(h, &sq[q], &cq[q]);
    }
    float A = 1.f;
    #pragma unroll
    for (int q = 0; q < 5; ++q)
        A *= ((lane >> (4 - q)) & 1) ? sq[q] : cq[q];

    float m[16];
    m[0] = A;
    #pragma unroll
    for (int t = 0; t < 4; ++t) {
        const int q = 8 - t;
        const int sz = 1 << t;
        #pragma unroll
        for (int k = sz - 1; k >= 0; --k) {
            float v = m[k];
            m[k + sz] = v * sq[q];
            m[k]      = v * cq[q];
        }
    }
    float2 sr[16], si[16];
    #pragma unroll
    for (int k = 0; k < 16; ++k) {
        float4 t = __ldg(&g_T0[k * 32 + lane]);
        float2 mag2 = make_float2(m[k] * cq[9], m[k] * sq[9]);
        sr[k] = fmul2_(mag2, make_float2(t.x, t.z));
        si[k] = fmul2_(mag2, make_float2(t.y, t.w));
    }

    // --- circuit -------------------------------------------------------------
    remaining_gates<0, 0>(sr, si, lane, g_ry[0]);   // Y_0 (no preceding P)
    fused_layer<1>(sr, si, lane);
    fused_layer<2>(sr, si, lane);
    fused_layer<3>(sr, si, lane);
    fused_layer<4>(sr, si, lane);
    fused_layer<5>(sr, si, lane);
    // P_5 (r=6) fully virtualized into the epilogue weights below.

    // --- epilogue: out = sum_m w_m |psi_m|^2, w from precomputed table -------
    float2 acc2 = make_float2(0.f, 0.f);
    #pragma unroll
    for (int k = 0; k < 16; ++k) {
        float2 w2 = __ldg(&g_W[k * 32 + lane]);
        float2 p2 = ffma2_(si[k], si[k], fmul2_(sr[k], sr[k]));
        acc2 = ffma2_(w2, p2, acc2);
    }
    float acc = acc2.x + acc2.y;
    #pragma unroll
    for (int off = 16; off; off >>= 1)
        acc += __shfl_xor_sync(0xffffffffu, acc, off);

    if (lane == 0) out[warp] = acc + __ldg(fc_b);
}

// ---------------------------------------------------------------------------
extern "C" void kernel_launch(void* const* d_in, const int* in_sizes, int n_in,
                              void* d_out, int out_size) {
    const float* x    = (const float*)d_in[0];   // (16384, 10)
    const float* ql   = (const float*)d_in[1];   // (6, 10, 3)
    const float* fcw  = (const float*)d_in[2];   // (1, 10)
    const float* fcb  = (const float*)d_in[3];   // (1,)
    float* out = (float*)d_out;                  // (16384, 1)

    table_kernel<<<2, 256>>>(ql, fcw);
    qcnn_kernel<<<BATCH / 8, 256>>>(x, fcb, out);
}

// round 9
// speedup vs baseline: 1.2554x; 1.1014x over previous
#include <cuda_runtime.h>

#define NQ      10
#define DIM     1024
#define NLAYERS 6
#define BATCH   16384

// Precomputed tables (sample-independent):
//  g_ry[l][q] = (cos θ/2, sin θ/2)
//  g_T0[idx]  = init phase pairs: (-i)^popc(n) * Dphi_0[n]
//  g_E[l-1][idx] = fused diagonal between RY layer l-1 and l (Λ-baked)
//  g_W[idx]   = epilogue weights (S6^{-1} and Λ_5 baked)
// idx = k*32 + lane (physical); pair covers local pack k, components 0/1.
__device__ float2 g_ry[NLAYERS][NQ];
__device__ __align__(16) float4 g_T0[512];
__device__ __align__(16) float4 g_E[5][512];
__device__ __align__(8)  float2 g_W[512];

// ---------------------------------------------------------------------------
// GF(2) algebra.
// s6inv_map: applies S6^{-1} (final CNOT layer, r=6) to a 10-bit index.
// lam_after(L, v): accumulated lane permutation Λ_L (physical lane -> logical
//   lane) after absorbing the lane/lane taus of permutation blocks 1..L.
//   Block l's lane/lane taus (shift r=l): w = 0..4-l, lane-space (4-w)->(4-w-l),
//   applied chronologically.
// inv_mask(L, b) = Λ_L^{-1}(e_b): the physical shfl_xor mask for logical bit b.
// row_mask(L, b): bit_b(Λ_L(p)) = parity(p & row_mask).
// ---------------------------------------------------------------------------
__host__ __device__ constexpr int s6inv_map(int m) {
    for (int w = 0; w < 10; ++w) {
        int cb = 9 - w, tb = 9 - ((w + 6) % 10);
        m ^= ((m >> cb) & 1) << tb;
    }
    return m;
}
__host__ __device__ constexpr int lam_after(int L, int v) {
    for (int l = 1; l <= L; ++l)
        for (int w = 0; w + l <= 4; ++w) {
            int c = 4 - w, t = 4 - w - l;
            v ^= ((v >> c) & 1) << t;
        }
    return v;
}
__host__ __device__ constexpr int inv_mask(int L, int b) {
    for (int v = 1; v < 32; ++v)
        if (lam_after(L, v) == (1 << b)) return v;
    return 0;
}
__host__ __device__ constexpr int row_mask(int L, int b) {
    int r = 0;
    for (int j = 0; j < 5; ++j)
        r |= ((lam_after(L, 1 << j) >> b) & 1) << j;
    return r;
}

// ---------------------------------------------------------------------------
// Packed f32x2 helpers (SASS FFMA2/FMUL2 — ptxas never emits these from C++)
// ---------------------------------------------------------------------------
__device__ __forceinline__ float2 ffma2_(float2 a, float2 b, float2 c) {
    float2 d;
    asm("{\n\t.reg .b64 A,B,C,D;\n\t"
        "mov.b64 A,{%2,%3};\n\t mov.b64 B,{%4,%5};\n\t mov.b64 C,{%6,%7};\n\t"
        "fma.rn.f32x2 D,A,B,C;\n\t"
        "mov.b64 {%0,%1},D;\n\t}"
        : "=f"(d.x), "=f"(d.y)
        : "f"(a.x), "f"(a.y), "f"(b.x), "f"(b.y), "f"(c.x), "f"(c.y));
    return d;
}
__device__ __forceinline__ float2 fmul2_(float2 a, float2 b) {
    float2 d;
    asm("{\n\t.reg .b64 A,B,D;\n\t"
        "mov.b64 A,{%2,%3};\n\t mov.b64 B,{%4,%5};\n\t"
        "mul.rn.f32x2 D,A,B;\n\t"
        "mov.b64 {%0,%1},D;\n\t}"
        : "=f"(d.x), "=f"(d.y)
        : "f"(a.x), "f"(a.y), "f"(b.x), "f"(b.y));
    return d;
}
__device__ __forceinline__ float2 fsub2_(float2 a, float2 b) {
    float2 d;
    asm("{\n\t.reg .b64 A,B,D;\n\t"
        "mov.b64 A,{%2,%3};\n\t mov.b64 B,{%4,%5};\n\t"
        "sub.rn.f32x2 D,A,B;\n\t"
        "mov.b64 {%0,%1},D;\n\t}"
        : "=f"(d.x), "=f"(d.y)
        : "f"(a.x), "f"(a.y), "f"(b.x), "f"(b.y));
    return d;
}
__device__ __forceinline__ float2 bc2(float v) { return make_float2(v, v); }

// ---------------------------------------------------------------------------
// Pre-kernel: RY coefficients + phase tables + epilogue weights, Λ-baked.
// ---------------------------------------------------------------------------
__device__ __forceinline__ float sum_signed(int n, const float* ql, int l, int off) {
    float a = 0.f;
    #pragma unroll
    for (int q = 0; q < NQ; ++q) {
        float v = ql[(l * NQ + q) * 3 + off];
        a += ((n >> (9 - q)) & 1) ? v : -v;
    }
    return 0.5f * a;
}

__global__ void table_kernel(const float* __restrict__ ql,
                             const float* __restrict__ fcw) {
    int idx = blockIdx.x * blockDim.x + threadIdx.x;
    if (idx < NLAYERS * NQ) {
        int l = idx / NQ, q = idx % NQ;
        float s, c; sincosf(0.5f * ql[(l * NQ + q) * 3 + 1], &s, &c);
        g_ry[l][q] = make_float2(c, s);
    }
    if (idx >= 512) return;
    int k = idx >> 5, lane = idx & 31;

    {   // T0 (applied with Λ = identity): (-i)^popc(n) * Dphi_0[n]
        float cs[2], sn[2];
        #pragma unroll
        for (int comp = 0; comp < 2; ++comp) {
            int n = (lane << 5) | (k << 1) | comp;
            float ang = -1.57079632679f * __popc(n) + sum_signed(n, ql, 0, 0);
            sincosf(ang, &sn[comp], &cs[comp]);
        }
        g_T0[idx] = make_float4(cs[0], sn[0], cs[1], sn[1]);
    }
    // E_l for l = 1..5, applied with Λ_{l-1} (before block-l lane/lane taus):
    // E[m] = Domega_{l-1}[m] * Dphi_l[sigma_{l-1}^{-1}(m)]
    #pragma unroll 1
    for (int l = 1; l <= 5; ++l) {
        int llog = lam_after(l - 1, lane);
        float cs[2], sn[2];
        #pragma unroll
        for (int comp = 0; comp < 2; ++comp) {
            int n = (llog << 5) | (k << 1) | comp;
            float angw = sum_signed(n, ql, l - 1, 2);
            int p = n;             // sigma^{-1}: apply tau_0 .. tau_9 in order
            #pragma unroll
            for (int w = 0; w < NQ; ++w) {
                int cbit = 9 - w;
                int tbit = 9 - ((w + l) % NQ);
                p ^= ((p >> cbit) & 1) << tbit;
            }
            float angp = sum_signed(p, ql, l, 0);
            sincosf(angw + angp, &sn[comp], &cs[comp]);
        }
        g_E[l - 1][idx] = make_float4(cs[0], sn[0], cs[1], sn[1]);
    }
    {   // Epilogue weights with Λ_5 and S6^{-1} baked:
        int llog = lam_after(5, lane);
        float wv[2];
        #pragma unroll
        for (int comp = 0; comp < 2; ++comp) {
            int n = (llog << 5) | (k << 1) | comp;
            int p = s6inv_map(n);
            float a = 0.f;
            #pragma unroll
            for (int q = 0; q < NQ; ++q) {
                float v = fcw[q];
                a += ((p >> (9 - q)) & 1) ? -v : v;
            }
            wv[comp] = a;
        }
        g_W[idx] = make_float2(wv[0], wv[1]);
    }
}

// ---------------------------------------------------------------------------
// State layout: logical amplitude n: bits 9..5 lane (via Λ), 4..1 pack k,
// 0 comp. Qubit q acts on logical bit 9-q. Lane bits are permuted by the
// deferred lane/lane CNOTs; Λ_L handled at compile time.
// ---------------------------------------------------------------------------

// RY gate on logical lane-space bit B5 (layer-block context L for Λ).
template<int L, int B5>
__device__ __forceinline__ void ry_lane_gate(float2 sr[16], float2 si[16], int lane,
                                             float2 g) {
    constexpr unsigned msk = (unsigned)inv_mask(L, B5);
    constexpr int row = row_mask(L, B5);
    const bool hi = __popc(lane & row) & 1;
    const float2 c2 = bc2(g.x);
    const float2 s2 = bc2(hi ? g.y : -g.y);
    #pragma unroll
    for (int k = 0; k < 16; ++k) {
        float2 qr, qi;
        qr.x = __shfl_xor_sync(0xffffffffu, sr[k].x, msk);
        qr.y = __shfl_xor_sync(0xffffffffu, sr[k].y, msk);
        qi.x = __shfl_xor_sync(0xffffffffu, si[k].x, msk);
        qi.y = __shfl_xor_sync(0xffffffffu, si[k].y, msk);
        sr[k] = ffma2_(s2, qr, fmul2_(c2, sr[k]));
        si[k] = ffma2_(s2, qi, fmul2_(c2, si[k]));
    }
}

// Plain RY gate on local bit B (1..4 = pack bit B-1; 0 = comp bit).
template<int B>
__device__ __forceinline__ void ry_local_gate(float2 sr[16], float2 si[16], float2 g) {
    if constexpr (B >= 1) {
        constexpr int pb = B - 1;
        const float2 cl2 = bc2(g.x), sl2 = bc2(g.y), nsl2 = bc2(-g.y);
        #pragma unroll
        for (int t = 0; t < 8; ++t) {
            const int k  = ((t >> pb) << (pb + 1)) | (t & ((1 << pb) - 1));
            const int k2 = k | (1 << pb);
            float2 Ar = sr[k], Ai = si[k], Br = sr[k2], Bi = si[k2];
            sr[k]  = ffma2_(nsl2, Br, fmul2_(cl2, Ar));
            si[k]  = ffma2_(nsl2, Bi, fmul2_(cl2, Ai));
            sr[k2] = ffma2_(cl2, Br, fmul2_(sl2, Ar));
            si[k2] = ffma2_(cl2, Bi, fmul2_(sl2, Ai));
        }
    } else {
        const float2 c2 = bc2(g.x);
        const float2 sp2 = make_float2(-g.y, g.y);
        #pragma unroll
        for (int k = 0; k < 16; ++k) {
            float2 vr = sr[k], vi = si[k];
            float2 wr = make_float2(vr.y, vr.x);
            float2 wi = make_float2(vi.y, vi.x);
            sr[k] = ffma2_(sp2, wr, fmul2_(c2, vr));
            si[k] = ffma2_(sp2, wi, fmul2_(c2, vi));
        }
    }
}

// Fused stage: CNOT(local control bit Bc -> logical lane bit B5) + RY(target).
template<int L, int Bc, int B5>
__device__ __forceinline__ void fused_cnot_ry(float2 sr[16], float2 si[16], int lane,
                                              float2 g) {
    constexpr unsigned msk = (unsigned)inv_mask(L, B5);
    constexpr int row = row_mask(L, B5);
    const bool hi = __popc(lane & row) & 1;
    const float sg = hi ? g.y : -g.y;
    if constexpr (Bc == 0) {
        const float2 A = make_float2(g.x, sg);
        const float2 B = make_float2(sg, g.x);
        #pragma unroll
        for (int k = 0; k < 16; ++k) {
            float2 qr, qi;
            qr.x = __shfl_xor_sync(0xffffffffu, sr[k].x, msk);
            qr.y = __shfl_xor_sync(0xffffffffu, sr[k].y, msk);
            qi.x = __shfl_xor_sync(0xffffffffu, si[k].x, msk);
            qi.y = __shfl_xor_sync(0xffffffffu, si[k].y, msk);
            sr[k] = ffma2_(B, qr, fmul2_(A, sr[k]));
            si[k] = ffma2_(B, qi, fmul2_(A, si[k]));
        }
    } else {
        const float2 c2 = bc2(g.x), s2 = bc2(sg);
        #pragma unroll
        for (int k = 0; k < 16; ++k) {
            float2 qr, qi;
            qr.x = __shfl_xor_sync(0xffffffffu, sr[k].x, msk);
            qr.y = __shfl_xor_sync(0xffffffffu, sr[k].y, msk);
            qi.x = __shfl_xor_sync(0xffffffffu, si[k].x, msk);
            qi.y = __shfl_xor_sync(0xffffffffu, si[k].y, msk);
            const bool ctl = (k >> (Bc - 1)) & 1;       // compile-time after unroll
            const float2 A = ctl ? s2 : c2;
            const float2 B = ctl ? c2 : s2;
            sr[k] = ffma2_(B, qr, fmul2_(A, sr[k]));
            si[k] = ffma2_(B, qi, fmul2_(A, si[k]));
        }
    }
}

// ---------------------------------------------------------------------------
// Standalone CNOT: control bit BC, target bit BT (logical).
// Lane/lane taus never reach here (deferred into Λ). Lane controls read the
// logical bit via Λ's row parity.
// ---------------------------------------------------------------------------
template<int L, int BC, int BT>
__device__ __forceinline__ void cnot_gate(float2 sr[16], float2 si[16], int lane) {
    if constexpr (BC >= 5 && BT >= 1) {
        constexpr int pb = BT - 1;
        constexpr int row = row_mask(L, BC - 5);
        const bool ctl = __popc(lane & row) & 1;
        #pragma unroll
        for (int k = 0; k < 16; ++k) {
            if (!((k >> pb) & 1)) {
                const int k2 = k | (1 << pb);
                float2 r0 = sr[k], r1 = sr[k2];
                float2 i0 = si[k], i1 = si[k2];
                sr[k].x  = ctl ? r1.x : r0.x;  sr[k].y  = ctl ? r1.y : r0.y;
                sr[k2].x = ctl ? r0.x : r1.x;  sr[k2].y = ctl ? r0.y : r1.y;
                si[k].x  = ctl ? i1.x : i0.x;  si[k].y  = ctl ? i1.y : i0.y;
                si[k2].x = ctl ? i0.x : i1.x;  si[k2].y = ctl ? i0.y : i1.y;
            }
        }
    } else if constexpr (BC >= 5 && BT == 0) {
        constexpr int row = row_mask(L, BC - 5);
        const bool ctl = __popc(lane & row) & 1;
        #pragma unroll
        for (int k = 0; k < 16; ++k) {
            float2 vr = sr[k], vi = si[k];
            sr[k].x = ctl ? vr.y : vr.x;  sr[k].y = ctl ? vr.x : vr.y;
            si[k].x = ctl ? vi.y : vi.x;  si[k].y = ctl ? vi.x : vi.y;
        }
    } else if constexpr (BC >= 1 && BT >= 1) {
        constexpr int pbc = BC - 1, pbt = BT - 1;
        #pragma unroll
        for (int k = 0; k < 16; ++k) {
            if (((k >> pbc) & 1) && !((k >> pbt) & 1)) {
                const int k2 = k | (1 << pbt);
                float2 t;
                t = sr[k]; sr[k] = sr[k2]; sr[k2] = t;
                t = si[k]; si[k] = si[k2]; si[k2] = t;
            }
        }
    } else {   // BC >= 1, BT == 0
        constexpr int pb = BC - 1;
        #pragma unroll
        for (int k = 0; k < 16; ++k) {
            if ((k >> pb) & 1) {
                float t;
                t = sr[k].x; sr[k].x = sr[k].y; sr[k].y = t;
                t = si[k].x; si[k].x = si[k].y; si[k].y = t;
            }
        }
    }
}

// fused diagonal: per pack complex multiply by table phase (Λ-baked table)
__device__ __forceinline__ void apply_diag(float2 sr[16], float2 si[16], int lane,
                                           const float4* __restrict__ tbl) {
    #pragma unroll
    for (int k = 0; k < 16; ++k) {
        float4 t = __ldg(tbl + k * 32 + lane);
        float2 c = make_float2(t.x, t.z);
        float2 s = make_float2(t.y, t.w);
        float2 r = sr[k], i = si[k];
        sr[k] = fsub2_(fmul2_(c, r), fmul2_(s, i));
        si[k] = ffma2_(c, i, fmul2_(s, r));
    }
}

// ---------------------------------------------------------------------------
// Block L (shift r = L):
//  1. diag E_L (table baked with Λ_{L-1})
//  2. lane/lane taus w = 0..4-L: DEFERRED into Λ (free)
//  3. standalone taus w = 5-L..9-L  (lane-ctrl/local-tgt, then local/local)
//  4. fused stages   w = 10-L..9: CNOT(local ctl -> lane tgt) + RY
//  5. remaining RY gates q = L..9
// ---------------------------------------------------------------------------
template<int L, int W>
__device__ __forceinline__ void standalone_taus(float2 sr[16], float2 si[16], int lane) {
    if constexpr (W <= 9 - L) {
        cnot_gate<L, 9 - W, 9 - W - L>(sr, si, lane);
        standalone_taus<L, W + 1>(sr, si, lane);
    }
}
template<int L, int W>
__device__ __forceinline__ void fused_stages(float2 sr[16], float2 si[16], int lane,
                                             const float2* __restrict__ ry) {
    if constexpr (W <= 9) {
        constexpr int Bc = 9 - W;          // local control bit (0..L-1)
        constexpr int B5 = 14 - W - L;     // logical lane-space target bit (0..4)
        fused_cnot_ry<L, Bc, B5>(sr, si, lane, __ldg(ry + (W + L - 10)));
        fused_stages<L, W + 1>(sr, si, lane, ry);
    }
}
template<int L, int Q>
__device__ __forceinline__ void remaining_gates(float2 sr[16], float2 si[16], int lane,
                                                const float2* __restrict__ ry) {
    if constexpr (Q <= 9) {
        if constexpr (Q <= 4)
            ry_lane_gate<L, 4 - Q>(sr, si, lane, __ldg(ry + Q));
        else
            ry_local_gate<9 - Q>(sr, si, __ldg(ry + Q));
        remaining_gates<L, Q + 1>(sr, si, lane, ry);
    }
}
template<int L>
__device__ __forceinline__ void fused_layer(float2 sr[16], float2 si[16], int lane) {
    apply_diag(sr, si, lane, g_E[L - 1]);
    standalone_taus<L, 5 - L>(sr, si, lane);   // lane/lane (w < 5-L) deferred
    fused_stages<L, 10 - L>(sr, si, lane, g_ry[L]);
    remaining_gates<L, L>(sr, si, lane, g_ry[L]);
}

// ---------------------------------------------------------------------------
// Main kernel: one warp per sample; 256 thr, 2 CTAs/SM (128 regs, no spill).
// ---------------------------------------------------------------------------
__global__ void __launch_bounds__(256, 2) qcnn_kernel(
    const float* __restrict__ x,
    const float* __restrict__ fc_b,
    float* __restrict__ out)
{
    const int warp = (blockIdx.x * blockDim.x + threadIdx.x) >> 5;
    const int lane = threadIdx.x & 31;
    if (warp >= BATCH) return;

    // --- initial product state magnitudes (Λ = identity here) ---------------
    const float* xb = x + warp * NQ;
    float cq[NQ], sq[NQ];
    #pragma unroll
    for (int q = 0; q < NQ; ++q) {
        float h = 0.5f * __ldg(xb + q);
        sincosf(h, &sq[q], &cq[q]);
    }
    float A = 1.f;
    #pragma unroll
    for (int q = 0; q < 5; ++q)
        A *= ((lane >> (4 - q)) & 1) ? sq[q] : cq[q];

    float m[16];
    m[0] = A;
    #pragma unroll
    for (int t = 0; t < 4; ++t) {
        const int q = 8 - t;
        const int sz = 1 << t;
        #pragma unroll
        for (int k = sz - 1; k >= 0; --k) {
            float v = m[k];
            m[k + sz] = v * sq[q];
            m[k]      = v * cq[q];
        }
    }
    float2 sr[16], si[16];
    #pragma unroll
    for (int k = 0; k < 16; ++k) {
        float4 t = __ldg(&g_T0[k * 32 + lane]);
        float2 mag2 = make_float2(m[k] * cq[9], m[k] * sq[9]);
        sr[k] = fmul2_(mag2, make_float2(t.x, t.z));
        si[k] = fmul2_(mag2, make_float2(t.y, t.w));
    }

    // --- circuit -------------------------------------------------------------
    remaining_gates<0, 0>(sr, si, lane, g_ry[0]);   // Y_0 (Λ_0 = identity)
    fused_layer<1>(sr, si, lane);
    fused_layer<2>(sr, si, lane);
    fused_layer<3>(sr, si, lane);
    fused_layer<4>(sr, si, lane);
    fused_layer<5>(sr, si, lane);
    // P_5 (r=6) and Λ_5 fully virtualized into the epilogue weight table.

    // --- epilogue: out = sum_m w_m |psi_m|^2, w from precomputed table -------
    float2 acc2 = make_float2(0.f, 0.f);
    #pragma unroll
    for (int k = 0; k < 16; ++k) {
        float2 w2 = __ldg(&g_W[k * 32 + lane]);
        float2 p2 = ffma2_(si[k], si[k], fmul2_(sr[k], sr[k]));
        acc2 = ffma2_(w2, p2, acc2);
    }
    float acc = acc2.x + acc2.y;
    #pragma unroll
    for (int off = 16; off; off >>= 1)
        acc += __shfl_xor_sync(0xffffffffu, acc, off);

    if (lane == 0) out[warp] = acc + __ldg(fc_b);
}

// ---------------------------------------------------------------------------
extern "C" void kernel_launch(void* const* d_in, const int* in_sizes, int n_in,
                              void* d_out, int out_size) {
    const float* x    = (const float*)d_in[0];   // (16384, 10)
    const float* ql   = (const float*)d_in[1];   // (6, 10, 3)
    const float* fcw  = (const float*)d_in[2];   // (1, 10)
    const float* fcb  = (const float*)d_in[3];   // (1,)
    float* out = (float*)d_out;                  // (16384, 1)

    table_kernel<<<2, 256>>>(ql, fcw);
    qcnn_kernel<<<BATCH / 8, 256>>>(x, fcb, out);
}